// round 6
// baseline (speedup 1.0000x reference)
#include <cuda_runtime.h>

// Problem constants: N=50000 nodes, D=64, E=800000 edges.
#define MAX_NODES   50000
#define MAX_EDGES   800000
#define DIM         64
#define SCAN_TPB    1024
#define MAX_SBLK    ((MAX_NODES + SCAN_TPB - 1) / SCAN_TPB)   // 49
#define NPAD        (MAX_SBLK * SCAN_TPB)                      // 50176

// Device-global scratch (no allocations allowed).
__device__ float g_emb[MAX_NODES * DIM];
__device__ float g_twohop[MAX_NODES * DIM];
__device__ int   g_cnt[2 * NPAD];       // [0:NPAD)=A counts, [NPAD:2*NPAD)=B counts
__device__ int   g_baseA[NPAD];
__device__ int   g_baseB[NPAD];
__device__ int   g_curA[NPAD];
__device__ int   g_curB[NPAD];
__device__ int   g_bsum[2 * MAX_SBLK];
__device__ int   g_eA[MAX_EDGES];       // packed: (src << 1) | (scale == 2)
__device__ int   g_eB[MAX_EDGES];       // src for e==3 edges

// K1: emb = elu(x*w) (float4 per thread) + fused per-dst counting,
// 4 edges per thread via int4 loads, fire-and-forget REDs.
// Requires g_cnt zeroed beforehand (memset node).
__global__ void k_emb_count(const float4* __restrict__ x,
                            const float4* __restrict__ w,
                            const int4* __restrict__ dst4,
                            const int4* __restrict__ ef4,
                            int total4, int n4) {
    int i = blockIdx.x * blockDim.x + threadIdx.x;
    if (i < total4) {
        float4 xv = x[i];
        float4 wv = w[i & (DIM / 4 - 1)];
        float4 e; float a;
        a = xv.x * wv.x; e.x = (a > 0.0f) ? a : expm1f(a);
        a = xv.y * wv.y; e.y = (a > 0.0f) ? a : expm1f(a);
        a = xv.z * wv.z; e.z = (a > 0.0f) ? a : expm1f(a);
        a = xv.w * wv.w; e.w = (a > 0.0f) ? a : expm1f(a);
        reinterpret_cast<float4*>(g_emb)[i] = e;
    }
    if (i < n4) {
        int4 d = dst4[i];
        int4 t = ef4[i];
        atomicAdd(&g_cnt[d.x], 1);
        atomicAdd(&g_cnt[d.y], 1);
        atomicAdd(&g_cnt[d.z], 1);
        atomicAdd(&g_cnt[d.w], 1);
        if (t.x == 3) atomicAdd(&g_cnt[NPAD + d.x], 1);
        if (t.y == 3) atomicAdd(&g_cnt[NPAD + d.y], 1);
        if (t.z == 3) atomicAdd(&g_cnt[NPAD + d.z], 1);
        if (t.w == 3) atomicAdd(&g_cnt[NPAD + d.w], 1);
    }
}

// K2: per-block exclusive scan (shuffle-based), emit block totals.
__global__ void k_scan1(int nblk) {
    __shared__ int warp_sums[32];
    int which = (blockIdx.x >= nblk) ? 1 : 0;
    int blk   = blockIdx.x - which * nblk;
    int idx   = blk * SCAN_TPB + threadIdx.x;
    int lane  = threadIdx.x & 31;
    int wid   = threadIdx.x >> 5;

    int v = g_cnt[which * NPAD + idx];
    int xi = v;
    #pragma unroll
    for (int o = 1; o < 32; o <<= 1) {
        int t = __shfl_up_sync(0xFFFFFFFFu, xi, o);
        if (lane >= o) xi += t;
    }
    if (lane == 31) warp_sums[wid] = xi;
    __syncthreads();
    if (wid == 0) {
        int s = warp_sums[lane];
        int y = s;
        #pragma unroll
        for (int o = 1; o < 32; o <<= 1) {
            int t = __shfl_up_sync(0xFFFFFFFFu, y, o);
            if (lane >= o) y += t;
        }
        warp_sums[lane] = y - s;                 // exclusive warp offsets
        if (lane == 31) g_bsum[which * nblk + blk] = y;  // block total
    }
    __syncthreads();
    int b = xi - v + warp_sums[wid];             // exclusive within block
    if (which) g_baseB[idx] = b;
    else       g_baseA[idx] = b;
}

// K3: add cross-block offsets and init cursors.
__global__ void k_scan2(int nblk) {
    __shared__ int sh[64];
    int which = (blockIdx.x >= nblk) ? 1 : 0;
    int blk   = blockIdx.x - which * nblk;
    int t     = threadIdx.x;

    if (t < 64) sh[t] = (t < blk) ? g_bsum[which * nblk + t] : 0;
    __syncthreads();
    if (t < 32) {
        int a = sh[t] + sh[t + 32];
        #pragma unroll
        for (int o = 16; o > 0; o >>= 1) a += __shfl_down_sync(0xFFFFFFFFu, a, o);
        if (t == 0) sh[0] = a;
    }
    __syncthreads();
    int off = sh[0];

    int idx = blk * SCAN_TPB + t;
    if (which) {
        int b = g_baseB[idx] + off;
        g_baseB[idx] = b;
        g_curB[idx]  = b;
    } else {
        int b = g_baseA[idx] + off;
        g_baseA[idx] = b;
        g_curA[idx]  = b;
    }
}

// K4: place edges into CSR slots — atomic cursors, 4 edges/thread (MLP=4).
__global__ void k_place(const int4* __restrict__ src4,
                        const int4* __restrict__ dst4,
                        const int4* __restrict__ ef4,
                        int n4) {
    int i = blockIdx.x * blockDim.x + threadIdx.x;
    if (i >= n4) return;
    int4 s = src4[i];
    int4 d = dst4[i];
    int4 t = ef4[i];

    int p0 = atomicAdd(&g_curA[d.x], 1);
    int p1 = atomicAdd(&g_curA[d.y], 1);
    int p2 = atomicAdd(&g_curA[d.z], 1);
    int p3 = atomicAdd(&g_curA[d.w], 1);
    g_eA[p0] = (s.x << 1) | ((t.x == 0) | (t.x == 4) | (t.x == 5));
    g_eA[p1] = (s.y << 1) | ((t.y == 0) | (t.y == 4) | (t.y == 5));
    g_eA[p2] = (s.z << 1) | ((t.z == 0) | (t.z == 4) | (t.z == 5));
    g_eA[p3] = (s.w << 1) | ((t.w == 0) | (t.w == 4) | (t.w == 5));

    if (t.x == 3) g_eB[atomicAdd(&g_curB[d.x], 1)] = s.x;
    if (t.y == 3) g_eB[atomicAdd(&g_curB[d.y], 1)] = s.y;
    if (t.z == 3) g_eB[atomicAdd(&g_curB[d.z], 1)] = s.z;
    if (t.w == 3) g_eB[atomicAdd(&g_curB[d.w], 1)] = s.w;
}

// K5: pull two-hop. 16 lanes per node, each lane owns one float4 of the row.
__global__ void k_gather_twohop(int n_nodes) {
    int gid  = blockIdx.x * blockDim.x + threadIdx.x;
    int node = gid >> 4;
    if (node >= n_nodes) return;
    int lane = gid & 15;
    int base = g_baseA[node];
    int cnt  = g_cnt[node];
    float4 acc = make_float4(0.f, 0.f, 0.f, 0.f);
    #pragma unroll 4
    for (int k = 0; k < cnt; k++) {
        int packed = g_eA[base + k];
        float scale = 1.0f + (float)(packed & 1);
        int s = packed >> 1;
        float4 v = *reinterpret_cast<const float4*>(g_emb + (size_t)s * DIM + lane * 4);
        acc.x += v.x * scale; acc.y += v.y * scale;
        acc.z += v.z * scale; acc.w += v.w * scale;
    }
    *reinterpret_cast<float4*>(g_twohop + (size_t)node * DIM + lane * 4) = acc;
}

// K6: pull one-hop (e==3): out[node] = sum twohop[src]. Writes every row.
__global__ void k_gather_onehop(float* __restrict__ out, int n_nodes) {
    int gid  = blockIdx.x * blockDim.x + threadIdx.x;
    int node = gid >> 4;
    if (node >= n_nodes) return;
    int lane = gid & 15;
    int base = g_baseB[node];
    int cnt  = g_cnt[NPAD + node];
    float4 acc = make_float4(0.f, 0.f, 0.f, 0.f);
    #pragma unroll 4
    for (int k = 0; k < cnt; k++) {
        int s = g_eB[base + k];
        float4 v = *reinterpret_cast<const float4*>(g_twohop + (size_t)s * DIM + lane * 4);
        acc.x += v.x; acc.y += v.y; acc.z += v.z; acc.w += v.w;
    }
    *reinterpret_cast<float4*>(out + (size_t)node * DIM + lane * 4) = acc;
}

extern "C" void kernel_launch(void* const* d_in, const int* in_sizes, int n_in,
                              void* d_out, int out_size) {
    const float* x   = (const float*)d_in[0];   // graph_embedding [N, D]
    const float* w   = (const float*)d_in[1];   // weight [1, D]
    const int*   src = (const int*)d_in[2];     // [E]
    const int*   dst = (const int*)d_in[3];     // [E]
    const int*   ef  = (const int*)d_in[4];     // [E]
    float* out = (float*)d_out;                 // [N, D]

    int total   = in_sizes[0];                  // N * D
    int n_edges = in_sizes[2];                  // E (assumed divisible by 4: 800000)
    int n_nodes = total / DIM;
    int total4  = total / 4;
    int n4      = n_edges / 4;
    int nblk    = (n_nodes + SCAN_TPB - 1) / SCAN_TPB;

    const int T = 256;

    // Zero counters via a memset node.
    void* cnt_ptr = nullptr;
    cudaGetSymbolAddress(&cnt_ptr, g_cnt);
    cudaMemsetAsync(cnt_ptr, 0, 2 * NPAD * sizeof(int));

    // K1: emb + fused batched edge counting
    {
        int work = (total4 > n4) ? total4 : n4;
        k_emb_count<<<(work + T - 1) / T, T>>>((const float4*)x, (const float4*)w,
                                               (const int4*)dst, (const int4*)ef,
                                               total4, n4);
    }
    // K2/K3: scan (both CSRs)
    k_scan1<<<2 * nblk, SCAN_TPB>>>(nblk);
    k_scan2<<<2 * nblk, SCAN_TPB>>>(nblk);
    // K4: batched placement (MLP=4)
    k_place<<<(n4 + T - 1) / T, T>>>((const int4*)src, (const int4*)dst,
                                     (const int4*)ef, n4);
    // K5/K6: pull gathers (16 lanes per node)
    {
        int threads = n_nodes * 16;
        k_gather_twohop<<<(threads + T - 1) / T, T>>>(n_nodes);
        k_gather_onehop<<<(threads + T - 1) / T, T>>>(out, n_nodes);
    }
}

// round 7
// speedup vs baseline: 1.0314x; 1.0314x over previous
#include <cuda_runtime.h>

// Problem constants: N=50000 nodes, D=64, E=800000 edges.
#define MAX_NODES   50000
#define MAX_EDGES   800000
#define DIM         64
#define SCAN_TPB    1024
#define MAX_SBLK    ((MAX_NODES + SCAN_TPB - 1) / SCAN_TPB)   // 49
#define NPAD        (MAX_SBLK * SCAN_TPB)                      // 50176

// Device-global scratch (no allocations allowed).
__device__ float g_emb[MAX_NODES * DIM];
__device__ float g_twohop[MAX_NODES * DIM];
__device__ int   g_cnt[NPAD];           // per-dst in-degree
__device__ int   g_base[NPAD];          // CSR row starts
__device__ int   g_bsum[MAX_SBLK];
__device__ int   g_rank[MAX_EDGES];     // edge rank within its dst
__device__ int   g_eA[MAX_EDGES];       // packed: (src<<2) | (two<<1) | (e==3)

// K1: emb = elu(x*w) (float4 per thread) + fused per-dst count with rank capture.
// Requires g_cnt zeroed beforehand (memset node).
__global__ void k_emb_count(const float4* __restrict__ x,
                            const float4* __restrict__ w,
                            const int* __restrict__ dst,
                            int total4, int n_edges) {
    int i = blockIdx.x * blockDim.x + threadIdx.x;
    if (i < total4) {
        float4 xv = x[i];
        float4 wv = w[i & (DIM / 4 - 1)];
        float4 e; float a;
        a = xv.x * wv.x; e.x = (a > 0.0f) ? a : expm1f(a);
        a = xv.y * wv.y; e.y = (a > 0.0f) ? a : expm1f(a);
        a = xv.z * wv.z; e.z = (a > 0.0f) ? a : expm1f(a);
        a = xv.w * wv.w; e.w = (a > 0.0f) ? a : expm1f(a);
        reinterpret_cast<float4*>(g_emb)[i] = e;
    }
    if (i < n_edges) {
        int d = dst[i];
        g_rank[i] = atomicAdd(&g_cnt[d], 1);
    }
}

// K2: per-block exclusive scan (shuffle-based), emit block totals.
__global__ void k_scan1() {
    __shared__ int warp_sums[32];
    int idx  = blockIdx.x * SCAN_TPB + threadIdx.x;
    int lane = threadIdx.x & 31;
    int wid  = threadIdx.x >> 5;

    int v = g_cnt[idx];
    int xi = v;
    #pragma unroll
    for (int o = 1; o < 32; o <<= 1) {
        int t = __shfl_up_sync(0xFFFFFFFFu, xi, o);
        if (lane >= o) xi += t;
    }
    if (lane == 31) warp_sums[wid] = xi;
    __syncthreads();
    if (wid == 0) {
        int s = warp_sums[lane];
        int y = s;
        #pragma unroll
        for (int o = 1; o < 32; o <<= 1) {
            int t = __shfl_up_sync(0xFFFFFFFFu, y, o);
            if (lane >= o) y += t;
        }
        warp_sums[lane] = y - s;                 // exclusive warp offsets
        if (lane == 31) g_bsum[blockIdx.x] = y;  // block total
    }
    __syncthreads();
    g_base[idx] = xi - v + warp_sums[wid];       // exclusive within block
}

// K3: add cross-block offsets.
__global__ void k_scan2() {
    __shared__ int sh[64];
    int blk = blockIdx.x;
    int t   = threadIdx.x;

    if (t < 64) sh[t] = (t < blk && t < MAX_SBLK) ? g_bsum[t] : 0;
    __syncthreads();
    if (t < 32) {
        int a = sh[t] + sh[t + 32];
        #pragma unroll
        for (int o = 16; o > 0; o >>= 1) a += __shfl_down_sync(0xFFFFFFFFu, a, o);
        if (t == 0) sh[0] = a;
    }
    __syncthreads();
    g_base[blk * SCAN_TPB + t] += sh[0];
}

// K4: place edges into CSR slots — deterministic, NO atomics.
__global__ void k_place(const int* __restrict__ src,
                        const int* __restrict__ dst,
                        const int* __restrict__ ef,
                        int n_edges) {
    int e = blockIdx.x * blockDim.x + threadIdx.x;
    if (e >= n_edges) return;
    int s = src[e], d = dst[e], t = ef[e];
    int r = g_rank[e];
    int two = (t == 0) | (t == 4) | (t == 5);
    g_eA[g_base[d] + r] = (s << 2) | (two << 1) | (t == 3);
}

// K5: pull two-hop. 16 lanes per node, each lane owns one float4 of the row.
__global__ void k_gather_twohop(int n_nodes) {
    int gid  = blockIdx.x * blockDim.x + threadIdx.x;
    int node = gid >> 4;
    if (node >= n_nodes) return;
    int lane = gid & 15;
    int base = g_base[node];
    int cnt  = g_cnt[node];
    float4 acc = make_float4(0.f, 0.f, 0.f, 0.f);
    #pragma unroll 4
    for (int k = 0; k < cnt; k++) {
        int packed = g_eA[base + k];
        float scale = 1.0f + (float)((packed >> 1) & 1);
        int s = packed >> 2;
        float4 v = *reinterpret_cast<const float4*>(g_emb + (size_t)s * DIM + lane * 4);
        acc.x += v.x * scale; acc.y += v.y * scale;
        acc.z += v.z * scale; acc.w += v.w * scale;
    }
    *reinterpret_cast<float4*>(g_twohop + (size_t)node * DIM + lane * 4) = acc;
}

// K6: pull one-hop: out[node] = sum over in-edges with e==3 of twohop[src].
// Reuses the A-CSR; flag bit 0 marks e==3 edges.
__global__ void k_gather_onehop(float* __restrict__ out, int n_nodes) {
    int gid  = blockIdx.x * blockDim.x + threadIdx.x;
    int node = gid >> 4;
    if (node >= n_nodes) return;
    int lane = gid & 15;
    int base = g_base[node];
    int cnt  = g_cnt[node];
    float4 acc = make_float4(0.f, 0.f, 0.f, 0.f);
    #pragma unroll 4
    for (int k = 0; k < cnt; k++) {
        int packed = g_eA[base + k];
        if (packed & 1) {
            int s = packed >> 2;
            float4 v = *reinterpret_cast<const float4*>(g_twohop + (size_t)s * DIM + lane * 4);
            acc.x += v.x; acc.y += v.y; acc.z += v.z; acc.w += v.w;
        }
    }
    *reinterpret_cast<float4*>(out + (size_t)node * DIM + lane * 4) = acc;
}

extern "C" void kernel_launch(void* const* d_in, const int* in_sizes, int n_in,
                              void* d_out, int out_size) {
    const float* x   = (const float*)d_in[0];   // graph_embedding [N, D]
    const float* w   = (const float*)d_in[1];   // weight [1, D]
    const int*   src = (const int*)d_in[2];     // [E]
    const int*   dst = (const int*)d_in[3];     // [E]
    const int*   ef  = (const int*)d_in[4];     // [E]
    float* out = (float*)d_out;                 // [N, D]

    int total   = in_sizes[0];                  // N * D
    int n_edges = in_sizes[2];                  // E
    int n_nodes = total / DIM;
    int total4  = total / 4;
    int nblk    = (n_nodes + SCAN_TPB - 1) / SCAN_TPB;

    const int T = 256;

    // Zero counters via a memset node.
    void* cnt_ptr = nullptr;
    cudaGetSymbolAddress(&cnt_ptr, g_cnt);
    cudaMemsetAsync(cnt_ptr, 0, NPAD * sizeof(int));

    // K1: emb + fused counting with rank capture
    {
        int work = (total4 > n_edges) ? total4 : n_edges;
        k_emb_count<<<(work + T - 1) / T, T>>>((const float4*)x, (const float4*)w,
                                               dst, total4, n_edges);
    }
    // K2/K3: scan (single CSR)
    k_scan1<<<nblk, SCAN_TPB>>>();
    k_scan2<<<nblk, SCAN_TPB>>>();
    // K4: deterministic placement
    k_place<<<(n_edges + T - 1) / T, T>>>(src, dst, ef, n_edges);
    // K5/K6: pull gathers (16 lanes per node)
    {
        int threads = n_nodes * 16;
        k_gather_twohop<<<(threads + T - 1) / T, T>>>(n_nodes);
        k_gather_onehop<<<(threads + T - 1) / T, T>>>(out, n_nodes);
    }
}

// round 8
// speedup vs baseline: 1.1651x; 1.1296x over previous
#include <cuda_runtime.h>

// Problem constants: N=50000 nodes, D=64, E=800000 edges.
#define MAX_NODES   50000
#define MAX_EDGES   800000
#define DIM         64
#define CAP         128          // per-node bucket capacity (expected max degree ~40)
#define OVF_MAX     8192

// Device-global scratch (no allocations allowed).
__device__ float g_emb[MAX_NODES * DIM];
__device__ float g_twohop[MAX_NODES * DIM];
__device__ int   g_cnt[MAX_NODES + 1];          // [MAX_NODES] = overflow counter
__device__ int   g_eA[MAX_NODES * CAP];         // packed: (src<<2)|(two<<1)|(e==3)
__device__ int   g_ovf[OVF_MAX * 2];            // (packed, dst) pairs

__device__ __forceinline__ void red_add_v4(float* p, float4 v) {
    asm volatile("red.global.add.v4.f32 [%0], {%1, %2, %3, %4};"
                 :: "l"(p), "f"(v.x), "f"(v.y), "f"(v.z), "f"(v.w)
                 : "memory");
}

// K1: emb = elu(x*w) (float4 per thread) + direct bucket insertion per edge.
// Requires g_cnt zeroed beforehand (memset node).
__global__ void k_emb_bucket(const float4* __restrict__ x,
                             const float4* __restrict__ w,
                             const int* __restrict__ src,
                             const int* __restrict__ dst,
                             const int* __restrict__ ef,
                             int total4, int n_edges) {
    int i = blockIdx.x * blockDim.x + threadIdx.x;
    if (i < total4) {
        float4 xv = x[i];
        float4 wv = w[i & (DIM / 4 - 1)];
        float4 e; float a;
        a = xv.x * wv.x; e.x = (a > 0.0f) ? a : expm1f(a);
        a = xv.y * wv.y; e.y = (a > 0.0f) ? a : expm1f(a);
        a = xv.z * wv.z; e.z = (a > 0.0f) ? a : expm1f(a);
        a = xv.w * wv.w; e.w = (a > 0.0f) ? a : expm1f(a);
        reinterpret_cast<float4*>(g_emb)[i] = e;
    }
    if (i < n_edges) {
        int s = src[i], d = dst[i], t = ef[i];
        int two = (t == 0) | (t == 4) | (t == 5);
        int packed = (s << 2) | (two << 1) | (t == 3);
        int slot = atomicAdd(&g_cnt[d], 1);
        if (slot < CAP) {
            g_eA[d * CAP + slot] = packed;
        } else {
            int o = atomicAdd(&g_cnt[MAX_NODES], 1);
            if (o < OVF_MAX) {
                g_ovf[2 * o]     = packed;
                g_ovf[2 * o + 1] = d;
            }
        }
    }
}

// K2: pull two-hop. 16 lanes per node, each lane owns one float4 of the row.
__global__ void k_gather_twohop(int n_nodes) {
    int gid  = blockIdx.x * blockDim.x + threadIdx.x;
    int node = gid >> 4;
    if (node >= n_nodes) return;
    int lane = gid & 15;
    int cnt  = g_cnt[node];
    if (cnt > CAP) cnt = CAP;
    const int* list = g_eA + node * CAP;
    float4 acc = make_float4(0.f, 0.f, 0.f, 0.f);
    #pragma unroll 4
    for (int k = 0; k < cnt; k++) {
        int packed = list[k];
        float scale = 1.0f + (float)((packed >> 1) & 1);
        int s = packed >> 2;
        float4 v = *reinterpret_cast<const float4*>(g_emb + (size_t)s * DIM + lane * 4);
        acc.x += v.x * scale; acc.y += v.y * scale;
        acc.z += v.z * scale; acc.w += v.w * scale;
    }
    *reinterpret_cast<float4*>(g_twohop + (size_t)node * DIM + lane * 4) = acc;
}

// K3: overflow fixup for two-hop (normally zero work).
__global__ void k_ovf_twohop() {
    int n = g_cnt[MAX_NODES];
    if (n > OVF_MAX) n = OVF_MAX;
    int lane = threadIdx.x & 15;
    for (int j = (blockIdx.x * blockDim.x + threadIdx.x) >> 4; j < n;
         j += (gridDim.x * blockDim.x) >> 4) {
        int packed = g_ovf[2 * j];
        int d      = g_ovf[2 * j + 1];
        int s = packed >> 2;
        float scale = 1.0f + (float)((packed >> 1) & 1);
        float4 v = *reinterpret_cast<const float4*>(g_emb + (size_t)s * DIM + lane * 4);
        v.x *= scale; v.y *= scale; v.z *= scale; v.w *= scale;
        red_add_v4(g_twohop + (size_t)d * DIM + lane * 4, v);
    }
}

// K4: pull one-hop: out[node] = sum over in-edges with e==3 of twohop[src].
__global__ void k_gather_onehop(float* __restrict__ out, int n_nodes) {
    int gid  = blockIdx.x * blockDim.x + threadIdx.x;
    int node = gid >> 4;
    if (node >= n_nodes) return;
    int lane = gid & 15;
    int cnt  = g_cnt[node];
    if (cnt > CAP) cnt = CAP;
    const int* list = g_eA + node * CAP;
    float4 acc = make_float4(0.f, 0.f, 0.f, 0.f);
    #pragma unroll 4
    for (int k = 0; k < cnt; k++) {
        int packed = list[k];
        if (packed & 1) {
            int s = packed >> 2;
            float4 v = *reinterpret_cast<const float4*>(g_twohop + (size_t)s * DIM + lane * 4);
            acc.x += v.x; acc.y += v.y; acc.z += v.z; acc.w += v.w;
        }
    }
    *reinterpret_cast<float4*>(out + (size_t)node * DIM + lane * 4) = acc;
}

// K5: overflow fixup for one-hop (normally zero work).
__global__ void k_ovf_onehop(float* __restrict__ out) {
    int n = g_cnt[MAX_NODES];
    if (n > OVF_MAX) n = OVF_MAX;
    int lane = threadIdx.x & 15;
    for (int j = (blockIdx.x * blockDim.x + threadIdx.x) >> 4; j < n;
         j += (gridDim.x * blockDim.x) >> 4) {
        int packed = g_ovf[2 * j];
        if (!(packed & 1)) continue;
        int d = g_ovf[2 * j + 1];
        int s = packed >> 2;
        float4 v = *reinterpret_cast<const float4*>(g_twohop + (size_t)s * DIM + lane * 4);
        red_add_v4(out + (size_t)d * DIM + lane * 4, v);
    }
}

extern "C" void kernel_launch(void* const* d_in, const int* in_sizes, int n_in,
                              void* d_out, int out_size) {
    const float* x   = (const float*)d_in[0];   // graph_embedding [N, D]
    const float* w   = (const float*)d_in[1];   // weight [1, D]
    const int*   src = (const int*)d_in[2];     // [E]
    const int*   dst = (const int*)d_in[3];     // [E]
    const int*   ef  = (const int*)d_in[4];     // [E]
    float* out = (float*)d_out;                 // [N, D]

    int total   = in_sizes[0];                  // N * D
    int n_edges = in_sizes[2];                  // E
    int n_nodes = total / DIM;
    int total4  = total / 4;

    const int T = 256;

    // Zero counters (incl. overflow counter) via a memset node.
    void* cnt_ptr = nullptr;
    cudaGetSymbolAddress(&cnt_ptr, g_cnt);
    cudaMemsetAsync(cnt_ptr, 0, (MAX_NODES + 1) * sizeof(int));

    // K1: emb + direct bucket insertion
    {
        int work = (total4 > n_edges) ? total4 : n_edges;
        k_emb_bucket<<<(work + T - 1) / T, T>>>((const float4*)x, (const float4*)w,
                                                src, dst, ef, total4, n_edges);
    }
    // K2: two-hop gather (16 lanes per node)
    {
        int threads = n_nodes * 16;
        k_gather_twohop<<<(threads + T - 1) / T, T>>>(n_nodes);
    }
    // K3: overflow fixup (usually empty)
    k_ovf_twohop<<<4, T>>>();
    // K4: one-hop gather
    {
        int threads = n_nodes * 16;
        k_gather_onehop<<<(threads + T - 1) / T, T>>>(out, n_nodes);
    }
    // K5: overflow fixup for one-hop (usually empty)
    k_ovf_onehop<<<4, T>>>(out);
}

// round 9
// speedup vs baseline: 1.1749x; 1.0085x over previous
#include <cuda_runtime.h>

// Problem constants: N=50000 nodes, D=64, E=800000 edges.
#define MAX_NODES   50000
#define MAX_EDGES   800000
#define DIM         64
#define CAP         128          // per-node bucket capacity (expected max degree ~40)
#define CAP_B       32           // per-node e==3 bucket capacity (expected max ~12)
#define OVF_MAX     8192

// Device-global scratch (no allocations allowed).
__device__ float g_emb[MAX_NODES * DIM];
__device__ float g_twohop[MAX_NODES * DIM];
__device__ int   g_cnt[MAX_NODES];              // A counts
__device__ int   g_cntB[MAX_NODES + 2];         // B counts; [N]=ovfA ctr, [N+1]=ovfB ctr
__device__ int   g_eA[MAX_NODES * CAP];         // packed: (src<<1) | two
__device__ int   g_eB[MAX_NODES * CAP_B];       // src for e==3 edges
__device__ int   g_ovfA[OVF_MAX * 2];           // (packed, dst)
__device__ int   g_ovfB[OVF_MAX * 2];           // (src, dst)

__device__ __forceinline__ void red_add_v4(float* p, float4 v) {
    asm volatile("red.global.add.v4.f32 [%0], {%1, %2, %3, %4};"
                 :: "l"(p), "f"(v.x), "f"(v.y), "f"(v.z), "f"(v.w)
                 : "memory");
}

// K1: emb = elu(x*w) (float4 per thread) + direct bucket insertion per edge.
// Requires g_cnt/g_cntB zeroed beforehand (memset nodes).
__global__ void k_emb_bucket(const float4* __restrict__ x,
                             const float4* __restrict__ w,
                             const int* __restrict__ src,
                             const int* __restrict__ dst,
                             const int* __restrict__ ef,
                             int total4, int n_edges) {
    int i = blockIdx.x * blockDim.x + threadIdx.x;
    if (i < total4) {
        float4 xv = x[i];
        float4 wv = w[i & (DIM / 4 - 1)];
        float4 e; float a;
        a = xv.x * wv.x; e.x = (a > 0.0f) ? a : expm1f(a);
        a = xv.y * wv.y; e.y = (a > 0.0f) ? a : expm1f(a);
        a = xv.z * wv.z; e.z = (a > 0.0f) ? a : expm1f(a);
        a = xv.w * wv.w; e.w = (a > 0.0f) ? a : expm1f(a);
        reinterpret_cast<float4*>(g_emb)[i] = e;
    }
    if (i < n_edges) {
        int s = src[i], d = dst[i], t = ef[i];
        int two = (t == 0) | (t == 4) | (t == 5);
        int packed = (s << 1) | two;
        int slot = atomicAdd(&g_cnt[d], 1);
        if (slot < CAP) {
            g_eA[d * CAP + slot] = packed;
        } else {
            int o = atomicAdd(&g_cntB[MAX_NODES], 1);
            if (o < OVF_MAX) { g_ovfA[2 * o] = packed; g_ovfA[2 * o + 1] = d; }
        }
        if (t == 3) {
            int slotb = atomicAdd(&g_cntB[d], 1);
            if (slotb < CAP_B) {
                g_eB[d * CAP_B + slotb] = s;
            } else {
                int o = atomicAdd(&g_cntB[MAX_NODES + 1], 1);
                if (o < OVF_MAX) { g_ovfB[2 * o] = s; g_ovfB[2 * o + 1] = d; }
            }
        }
    }
}

// K2: pull two-hop. 16 lanes per node, each lane owns one float4 of the row.
__global__ void k_gather_twohop(int n_nodes) {
    int gid  = blockIdx.x * blockDim.x + threadIdx.x;
    int node = gid >> 4;
    if (node >= n_nodes) return;
    int lane = gid & 15;
    int cnt  = g_cnt[node];
    if (cnt > CAP) cnt = CAP;
    const int* list = g_eA + node * CAP;
    float4 acc = make_float4(0.f, 0.f, 0.f, 0.f);
    #pragma unroll 4
    for (int k = 0; k < cnt; k++) {
        int packed = list[k];
        float scale = 1.0f + (float)(packed & 1);
        int s = packed >> 1;
        float4 v = *reinterpret_cast<const float4*>(g_emb + (size_t)s * DIM + lane * 4);
        acc.x += v.x * scale; acc.y += v.y * scale;
        acc.z += v.z * scale; acc.w += v.w * scale;
    }
    *reinterpret_cast<float4*>(g_twohop + (size_t)node * DIM + lane * 4) = acc;
}

// K3: overflow fixup for two-hop (normally zero work).
__global__ void k_ovf_twohop() {
    int n = g_cntB[MAX_NODES];
    if (n > OVF_MAX) n = OVF_MAX;
    int lane = threadIdx.x & 15;
    for (int j = (blockIdx.x * blockDim.x + threadIdx.x) >> 4; j < n;
         j += (gridDim.x * blockDim.x) >> 4) {
        int packed = g_ovfA[2 * j];
        int d      = g_ovfA[2 * j + 1];
        int s = packed >> 1;
        float scale = 1.0f + (float)(packed & 1);
        float4 v = *reinterpret_cast<const float4*>(g_emb + (size_t)s * DIM + lane * 4);
        v.x *= scale; v.y *= scale; v.z *= scale; v.w *= scale;
        red_add_v4(g_twohop + (size_t)d * DIM + lane * 4, v);
    }
}

// K4: pull one-hop from dedicated e==3 buckets.
__global__ void k_gather_onehop(float* __restrict__ out, int n_nodes) {
    int gid  = blockIdx.x * blockDim.x + threadIdx.x;
    int node = gid >> 4;
    if (node >= n_nodes) return;
    int lane = gid & 15;
    int cnt  = g_cntB[node];
    if (cnt > CAP_B) cnt = CAP_B;
    const int* list = g_eB + node * CAP_B;
    float4 acc = make_float4(0.f, 0.f, 0.f, 0.f);
    #pragma unroll 2
    for (int k = 0; k < cnt; k++) {
        int s = list[k];
        float4 v = *reinterpret_cast<const float4*>(g_twohop + (size_t)s * DIM + lane * 4);
        acc.x += v.x; acc.y += v.y; acc.z += v.z; acc.w += v.w;
    }
    *reinterpret_cast<float4*>(out + (size_t)node * DIM + lane * 4) = acc;
}

// K5: overflow fixup for one-hop (normally zero work).
__global__ void k_ovf_onehop(float* __restrict__ out) {
    int n = g_cntB[MAX_NODES + 1];
    if (n > OVF_MAX) n = OVF_MAX;
    int lane = threadIdx.x & 15;
    for (int j = (blockIdx.x * blockDim.x + threadIdx.x) >> 4; j < n;
         j += (gridDim.x * blockDim.x) >> 4) {
        int s = g_ovfB[2 * j];
        int d = g_ovfB[2 * j + 1];
        float4 v = *reinterpret_cast<const float4*>(g_twohop + (size_t)s * DIM + lane * 4);
        red_add_v4(out + (size_t)d * DIM + lane * 4, v);
    }
}

extern "C" void kernel_launch(void* const* d_in, const int* in_sizes, int n_in,
                              void* d_out, int out_size) {
    const float* x   = (const float*)d_in[0];   // graph_embedding [N, D]
    const float* w   = (const float*)d_in[1];   // weight [1, D]
    const int*   src = (const int*)d_in[2];     // [E]
    const int*   dst = (const int*)d_in[3];     // [E]
    const int*   ef  = (const int*)d_in[4];     // [E]
    float* out = (float*)d_out;                 // [N, D]

    int total   = in_sizes[0];                  // N * D
    int n_edges = in_sizes[2];                  // E
    int n_nodes = total / DIM;
    int total4  = total / 4;

    const int T = 256;

    // Zero counters via memset nodes.
    void* p = nullptr;
    cudaGetSymbolAddress(&p, g_cnt);
    cudaMemsetAsync(p, 0, MAX_NODES * sizeof(int));
    cudaGetSymbolAddress(&p, g_cntB);
    cudaMemsetAsync(p, 0, (MAX_NODES + 2) * sizeof(int));

    // K1: emb + direct bucket insertion (A + B buckets)
    {
        int work = (total4 > n_edges) ? total4 : n_edges;
        k_emb_bucket<<<(work + T - 1) / T, T>>>((const float4*)x, (const float4*)w,
                                                src, dst, ef, total4, n_edges);
    }
    // K2: two-hop gather (16 lanes per node)
    {
        int threads = n_nodes * 16;
        k_gather_twohop<<<(threads + T - 1) / T, T>>>(n_nodes);
    }
    // K3: overflow fixup (usually empty)
    k_ovf_twohop<<<4, T>>>();
    // K4: one-hop gather from B buckets
    {
        int threads = n_nodes * 16;
        k_gather_onehop<<<(threads + T - 1) / T, T>>>(out, n_nodes);
    }
    // K5: overflow fixup for one-hop (usually empty)
    k_ovf_onehop<<<4, T>>>(out);
}